// round 10
// baseline (speedup 1.0000x reference)
#include <cuda_runtime.h>

#define BB 4
#define NN 8192
#define DD 16
#define RR 32
#define HH 64
#define EE 262144

typedef unsigned long long u64;

// ---- f32x2 packed-math helpers (full fp32 precision, 2x FFMA pipe tput) ----
__device__ __forceinline__ u64 pk2(float x, float y) {
    u64 r; asm("mov.b64 %0, {%1, %2};" : "=l"(r) : "f"(x), "f"(y)); return r;
}
__device__ __forceinline__ void up2(u64 v, float& x, float& y) {
    asm("mov.b64 {%0, %1}, %2;" : "=f"(x), "=f"(y) : "l"(v));
}
__device__ __forceinline__ void fma2(u64& d, u64 a, u64 b) {
    asm("fma.rn.f32x2 %0, %1, %2, %3;" : "=l"(d) : "l"(a), "l"(b), "l"(d));
}

// Scratch (allocation-free: __device__ globals)
__device__ float g_P1[BB * NN * HH];   // particles @ W1[:16] + b1
__device__ float g_P2[BB * NN * HH];   // particles @ W1[16:]
__device__ float g_rel[BB * NN * RR];  // scatter-add target

// ---------------------------------------------------------------------------
// Kernel A: per-node first-layer projections + zero rel. One thread per (b,n).
// 128-thread blocks -> grid 256 (>148 SMs) for SM fill.
// ---------------------------------------------------------------------------
__global__ __launch_bounds__(128) void node_proj_kernel(
    const float* __restrict__ particles,
    const float* __restrict__ W1,   // [32, 64] row-major
    const float* __restrict__ b1)   // [64]
{
    __shared__ float sW1[32 * 64];
    __shared__ float sb1[64];
    for (int i = threadIdx.x; i < 32 * 64; i += 128) sW1[i] = W1[i];
    if (threadIdx.x < 64) sb1[threadIdx.x] = b1[threadIdx.x];
    __syncthreads();

    int idx = blockIdx.x * 128 + threadIdx.x;  // 0 .. B*N-1

    float x[16];
    const float4* xp = (const float4*)(particles + (size_t)idx * 16);
    #pragma unroll
    for (int c = 0; c < 4; c++) {
        float4 v = xp[c];
        x[4 * c + 0] = v.x; x[4 * c + 1] = v.y; x[4 * c + 2] = v.z; x[4 * c + 3] = v.w;
    }

    float4* P1o = (float4*)(g_P1 + (size_t)idx * 64);
    float4* P2o = (float4*)(g_P2 + (size_t)idx * 64);

    #pragma unroll
    for (int c = 0; c < 16; c++) {
        float4 acc = ((const float4*)sb1)[c];
        #pragma unroll
        for (int i = 0; i < 16; i++) {
            float4 w = ((const float4*)(sW1 + i * 64))[c];
            acc.x += x[i] * w.x; acc.y += x[i] * w.y;
            acc.z += x[i] * w.z; acc.w += x[i] * w.w;
        }
        P1o[c] = acc;
    }
    #pragma unroll
    for (int c = 0; c < 16; c++) {
        float4 acc = make_float4(0.f, 0.f, 0.f, 0.f);
        #pragma unroll
        for (int i = 0; i < 16; i++) {
            float4 w = ((const float4*)(sW1 + (16 + i) * 64))[c];
            acc.x += x[i] * w.x; acc.y += x[i] * w.y;
            acc.z += x[i] * w.z; acc.w += x[i] * w.w;
        }
        P2o[c] = acc;
    }

    float4* relo = (float4*)(g_rel + (size_t)idx * 32);
    #pragma unroll
    for (int c = 0; c < 8; c++) relo[c] = make_float4(0.f, 0.f, 0.f, 0.f);
}

// ---------------------------------------------------------------------------
// Kernel B: edge MLP, WARP-AUTONOMOUS. Each warp owns 32 edges end-to-end
// with a private shH slice; no block-wide barriers inside the loop.
//   gather (per 32-k chunk): one warp inst fetches float4s of P1[s]
//     (side=0 lanes) and P2[r] (side=1 lanes) for 2 edges -> 4 lines/inst.
//     shfl_xor(8) combines sides, relu, store edge-major shH[e*33+k].
//   mma: lane = (jg = lane>>3, eg = lane&7); 4 edges {eg+8i} x 8 cols
//     (j0 = jg*8); weights broadcast from smem as u64 pairs; f32x2 FMAs.
// Epilogue: relu + red.global.add.v4.f32 scatter.
// ---------------------------------------------------------------------------
__global__ __launch_bounds__(256) void edge_kernel(
    const int* __restrict__ senders,
    const int* __restrict__ receivers,
    const float* __restrict__ W2,   // [64, 32] row-major
    const float* __restrict__ b2)   // [32]
{
    __shared__ float sW[64 * 32];
    __shared__ float sb2v[32];
    __shared__ float shH[8][32 * 33];   // per-warp slice, padded
    __shared__ int   sS[256], sR[256];

    int tid  = threadIdx.x;
    int base = blockIdx.x * 256;
    int b    = blockIdx.y;

    sS[tid] = senders[base + tid];
    sR[tid] = receivers[base + tid];
    for (int i = tid; i < 64 * 32; i += 256) sW[i] = W2[i];
    if (tid < 32) sb2v[tid] = b2[tid];
    __syncthreads();   // only block-wide barrier

    const float* P1b = g_P1 + (size_t)b * NN * 64;
    const float* P2b = g_P2 + (size_t)b * NN * 64;

    int lane = tid & 31;
    int w    = tid >> 5;            // warp id; owns edges w*32 .. w*32+31

    // gather roles
    int half = (lane >> 4) & 1;     // which of the 2 edges in this inst
    int side = (lane >> 3) & 1;     // 0 = P1[sender], 1 = P2[receiver]
    int c    = lane & 7;            // float4 chunk (k = 4c..4c+3)

    // mma roles
    int jg = lane >> 3;             // 0..3 -> output col group
    int eg = lane & 7;              // edges eg + 8*i
    int j0 = jg * 8;

    float* myH = shH[w];
    const int*   myIdx = side ? sR : sS;
    const float* myP   = side ? P2b : P1b;

    // accumulators: 4 edges x 8 cols as u64 pairs, init from b2
    u64 acc[4][4];
    {
        const u64* bp = (const u64*)&sb2v[j0];
        u64 c0 = bp[0], c1 = bp[1], c2 = bp[2], c3 = bp[3];
        #pragma unroll
        for (int i = 0; i < 4; i++) {
            acc[i][0] = c0; acc[i][1] = c1; acc[i][2] = c2; acc[i][3] = c3;
        }
    }

    #pragma unroll 1
    for (int ch = 0; ch < 2; ch++) {
        // ---------------- gather phase: warp's 32 edges, 32 k-values ------
        #pragma unroll 2
        for (int it = 0; it < 16; it++) {
            int eloc = it * 2 + half;               // 0..31
            int node = myIdx[w * 32 + eloc];
            float4 v = *((const float4*)(myP + (size_t)node * 64) + ch * 8 + c);
            float4 o;
            o.x = v.x + __shfl_xor_sync(0xffffffffu, v.x, 8);
            o.y = v.y + __shfl_xor_sync(0xffffffffu, v.y, 8);
            o.z = v.z + __shfl_xor_sync(0xffffffffu, v.z, 8);
            o.w = v.w + __shfl_xor_sync(0xffffffffu, v.w, 8);
            if (side == 0) {
                float* dst = &myH[eloc * 33 + 4 * c];
                dst[0] = fmaxf(o.x, 0.f);
                dst[1] = fmaxf(o.y, 0.f);
                dst[2] = fmaxf(o.z, 0.f);
                dst[3] = fmaxf(o.w, 0.f);
            }
        }
        __syncwarp();

        // ---------------- mma phase over k in [ch*32, ch*32+32) -----------
        #pragma unroll 4
        for (int kk = 0; kk < 32; kk++) {
            int k = ch * 32 + kk;
            const ulonglong2* wp = (const ulonglong2*)&sW[k * 32 + j0];
            ulonglong2 wa = wp[0];
            ulonglong2 wb = wp[1];
            #pragma unroll
            for (int i = 0; i < 4; i++) {
                float hv = myH[(eg + 8 * i) * 33 + kk];
                u64 hp = pk2(hv, hv);
                fma2(acc[i][0], hp, wa.x);
                fma2(acc[i][1], hp, wa.y);
                fma2(acc[i][2], hp, wb.x);
                fma2(acc[i][3], hp, wb.y);
            }
        }
        __syncwarp();
    }

    // ---------------- epilogue: relu + vector atomic scatter --------------
    float* relb = g_rel + (size_t)b * NN * 32;
    #pragma unroll
    for (int i = 0; i < 4; i++) {
        int r = sR[w * 32 + eg + 8 * i];
        float f[8];
        up2(acc[i][0], f[0], f[1]); up2(acc[i][1], f[2], f[3]);
        up2(acc[i][2], f[4], f[5]); up2(acc[i][3], f[6], f[7]);
        #pragma unroll
        for (int q = 0; q < 8; q++) f[q] = fmaxf(f[q], 0.f);
        float* ptr = relb + (size_t)r * 32 + j0;
        asm volatile("red.global.add.v4.f32 [%0], {%1, %2, %3, %4};"
                     :: "l"(ptr), "f"(f[0]), "f"(f[1]), "f"(f[2]), "f"(f[3]) : "memory");
        asm volatile("red.global.add.v4.f32 [%0], {%1, %2, %3, %4};"
                     :: "l"(ptr + 4), "f"(f[4]), "f"(f[5]), "f"(f[6]), "f"(f[7]) : "memory");
    }
}

// ---------------------------------------------------------------------------
// Kernel C: node MLP + residual. One thread per (b, n).
// 128-thread blocks -> grid 256 for SM fill.
// ---------------------------------------------------------------------------
__global__ __launch_bounds__(128) void node_out_kernel(
    const float* __restrict__ particles,
    const float* __restrict__ W3,   // [48, 64]
    const float* __restrict__ b3,   // [64]
    const float* __restrict__ W4,   // [64, 16]
    const float* __restrict__ b4,   // [16]
    float* __restrict__ out)
{
    __shared__ float sW3[48 * 64];
    __shared__ float sW4[64 * 16];
    __shared__ float sb3[64];
    __shared__ float sb4[16];
    for (int i = threadIdx.x; i < 48 * 64; i += 128) sW3[i] = W3[i];
    for (int i = threadIdx.x; i < 64 * 16; i += 128) sW4[i] = W4[i];
    if (threadIdx.x < 64) sb3[threadIdx.x] = b3[threadIdx.x];
    if (threadIdx.x < 16) sb4[threadIdx.x] = b4[threadIdx.x];
    __syncthreads();

    int idx = blockIdx.x * 128 + threadIdx.x;

    float x[48];
    const float4* pp = (const float4*)(particles + (size_t)idx * 16);
    #pragma unroll
    for (int c = 0; c < 4; c++) {
        float4 v = pp[c];
        x[4 * c + 0] = v.x; x[4 * c + 1] = v.y; x[4 * c + 2] = v.z; x[4 * c + 3] = v.w;
    }
    const float4* rp = (const float4*)(g_rel + (size_t)idx * 32);
    #pragma unroll
    for (int c = 0; c < 8; c++) {
        float4 v = rp[c];
        x[16 + 4 * c + 0] = v.x; x[16 + 4 * c + 1] = v.y;
        x[16 + 4 * c + 2] = v.z; x[16 + 4 * c + 3] = v.w;
    }

    float delta[16];
    #pragma unroll
    for (int j = 0; j < 16; j++) delta[j] = sb4[j];

    #pragma unroll
    for (int half = 0; half < 2; half++) {
        float t[32];
        #pragma unroll
        for (int j = 0; j < 32; j++) t[j] = sb3[half * 32 + j];

        #pragma unroll
        for (int i = 0; i < 48; i++) {
            const float4* w = (const float4*)(sW3 + i * 64 + half * 32);
            float xv = x[i];
            #pragma unroll
            for (int j = 0; j < 8; j++) {
                float4 wv = w[j];
                t[4 * j + 0] += xv * wv.x;
                t[4 * j + 1] += xv * wv.y;
                t[4 * j + 2] += xv * wv.z;
                t[4 * j + 3] += xv * wv.w;
            }
        }
        #pragma unroll
        for (int j = 0; j < 32; j++) t[j] = fmaxf(t[j], 0.f);

        #pragma unroll
        for (int i = 0; i < 32; i++) {
            const float4* w = (const float4*)(sW4 + (half * 32 + i) * 16);
            float tv = t[i];
            #pragma unroll
            for (int j = 0; j < 4; j++) {
                float4 wv = w[j];
                delta[4 * j + 0] += tv * wv.x;
                delta[4 * j + 1] += tv * wv.y;
                delta[4 * j + 2] += tv * wv.z;
                delta[4 * j + 3] += tv * wv.w;
            }
        }
    }

    float4* outp = (float4*)(out + (size_t)idx * 16);
    #pragma unroll
    for (int c = 0; c < 4; c++) {
        outp[c] = make_float4(x[4 * c + 0] + delta[4 * c + 0],
                              x[4 * c + 1] + delta[4 * c + 1],
                              x[4 * c + 2] + delta[4 * c + 2],
                              x[4 * c + 3] + delta[4 * c + 3]);
    }
}

extern "C" void kernel_launch(void* const* d_in, const int* in_sizes, int n_in,
                              void* d_out, int out_size)
{
    const float* particles = (const float*)d_in[0];
    const int*   senders   = (const int*)d_in[1];
    const int*   receivers = (const int*)d_in[2];
    const float* W1 = (const float*)d_in[3];
    const float* b1 = (const float*)d_in[4];
    const float* W2 = (const float*)d_in[5];
    const float* b2 = (const float*)d_in[6];
    const float* W3 = (const float*)d_in[7];
    const float* b3 = (const float*)d_in[8];
    const float* W4 = (const float*)d_in[9];
    const float* b4 = (const float*)d_in[10];
    float* out = (float*)d_out;

    node_proj_kernel<<<(BB * NN) / 128, 128>>>(particles, W1, b1);

    dim3 egrid(EE / 256, BB);
    edge_kernel<<<egrid, 256>>>(senders, receivers, W2, b2);

    node_out_kernel<<<(BB * NN) / 128, 128>>>(particles, W3, b3, W4, b4, out);
}

// round 12
// speedup vs baseline: 1.1508x; 1.1508x over previous
#include <cuda_runtime.h>

#define BB 4
#define NN 8192
#define DD 16
#define RR 32
#define HH 64
#define EE 262144

typedef unsigned long long u64;

// ---- f32x2 packed-math helpers (full fp32 precision, 2x FFMA pipe tput) ----
__device__ __forceinline__ u64 pk2(float x, float y) {
    u64 r; asm("mov.b64 %0, {%1, %2};" : "=l"(r) : "f"(x), "f"(y)); return r;
}
__device__ __forceinline__ void up2(u64 v, float& x, float& y) {
    asm("mov.b64 {%0, %1}, %2;" : "=f"(x), "=f"(y) : "l"(v));
}
__device__ __forceinline__ void fma2(u64& d, u64 a, u64 b) {
    asm("fma.rn.f32x2 %0, %1, %2, %3;" : "=l"(d) : "l"(a), "l"(b), "l"(d));
}

// Scratch (allocation-free: __device__ globals)
__device__ float g_P1[BB * NN * HH];   // particles @ W1[:16] + b1
__device__ float g_P2[BB * NN * HH];   // particles @ W1[16:]
__device__ float g_rel[BB * NN * RR];  // scatter-add target

// ---------------------------------------------------------------------------
// Kernel A (R3-proven config): per-node first-layer projections + zero rel.
// One thread per (b, n), 256-thread blocks, grid 128.
// ---------------------------------------------------------------------------
__global__ __launch_bounds__(256) void node_proj_kernel(
    const float* __restrict__ particles,
    const float* __restrict__ W1,   // [32, 64] row-major
    const float* __restrict__ b1)   // [64]
{
    __shared__ float sW1[32 * 64];
    __shared__ float sb1[64];
    for (int i = threadIdx.x; i < 32 * 64; i += 256) sW1[i] = W1[i];
    if (threadIdx.x < 64) sb1[threadIdx.x] = b1[threadIdx.x];
    __syncthreads();

    int idx = blockIdx.x * 256 + threadIdx.x;  // 0 .. B*N-1

    float x[16];
    const float4* xp = (const float4*)(particles + (size_t)idx * 16);
    #pragma unroll
    for (int c = 0; c < 4; c++) {
        float4 v = xp[c];
        x[4 * c + 0] = v.x; x[4 * c + 1] = v.y; x[4 * c + 2] = v.z; x[4 * c + 3] = v.w;
    }

    float4* P1o = (float4*)(g_P1 + (size_t)idx * 64);
    float4* P2o = (float4*)(g_P2 + (size_t)idx * 64);

    #pragma unroll
    for (int c = 0; c < 16; c++) {
        float4 acc = ((const float4*)sb1)[c];
        #pragma unroll
        for (int i = 0; i < 16; i++) {
            float4 w = ((const float4*)(sW1 + i * 64))[c];
            acc.x += x[i] * w.x; acc.y += x[i] * w.y;
            acc.z += x[i] * w.z; acc.w += x[i] * w.w;
        }
        P1o[c] = acc;
    }
    #pragma unroll
    for (int c = 0; c < 16; c++) {
        float4 acc = make_float4(0.f, 0.f, 0.f, 0.f);
        #pragma unroll
        for (int i = 0; i < 16; i++) {
            float4 w = ((const float4*)(sW1 + (16 + i) * 64))[c];
            acc.x += x[i] * w.x; acc.y += x[i] * w.y;
            acc.z += x[i] * w.z; acc.w += x[i] * w.w;
        }
        P2o[c] = acc;
    }

    float4* relo = (float4*)(g_rel + (size_t)idx * 32);
    #pragma unroll
    for (int c = 0; c < 8; c++) relo[c] = make_float4(0.f, 0.f, 0.f, 0.f);
}

// ---------------------------------------------------------------------------
// Kernel B: edge MLP. Warp owns 32 edges. shH is EDGE-MAJOR with row stride
// 36 floats (16B-aligned rows: 144B):
//   gather (per 32-k chunk, MLP=4): warp inst fetches float4s of P1[s]
//     (side=0 lanes) / P2[r] (side=1) for 2 edges -> 4 lines/inst;
//     shfl_xor(8) combines, relu, ONE STS.128 at shH[e*36 + 4c] (aligned,
//     ~2-phase).
//   mma: kk in blocks of 4. h via 4 LDS.128 (shH[(eg+8i)*36 + kkb], banks
//     4eg+kkb distinct, jg broadcast -> conflict-free); weights 2 broadcast
//     LDS.128 per kk; f32x2 FMAs. 12 LDS per 4 kk (was 24).
// Epilogue: relu + red.global.add.v4.f32 scatter.
// ---------------------------------------------------------------------------
__global__ __launch_bounds__(256) void edge_kernel(
    const int* __restrict__ senders,
    const int* __restrict__ receivers,
    const float* __restrict__ W2,   // [64, 32] row-major
    const float* __restrict__ b2)   // [32]
{
    __shared__ float sW[64 * 32];
    __shared__ float sb2v[32];
    __shared__ float shH[8][32 * 36];   // per-warp, edge-major, stride 36
    __shared__ int   sS[256], sR[256];

    int tid  = threadIdx.x;
    int base = blockIdx.x * 256;
    int b    = blockIdx.y;

    sS[tid] = senders[base + tid];
    sR[tid] = receivers[base + tid];
    for (int i = tid; i < 64 * 32; i += 256) sW[i] = W2[i];
    if (tid < 32) sb2v[tid] = b2[tid];
    __syncthreads();   // only block-wide barrier

    const float* P1b = g_P1 + (size_t)b * NN * 64;
    const float* P2b = g_P2 + (size_t)b * NN * 64;

    int lane = tid & 31;
    int w    = tid >> 5;            // warp id; owns edges w*32 .. w*32+31

    // gather roles
    int half = (lane >> 4) & 1;     // which of the 2 edges in this inst
    int side = (lane >> 3) & 1;     // 0 = P1[sender], 1 = P2[receiver]
    int c    = lane & 7;            // float4 chunk (k = 4c..4c+3 within chunk)

    // mma roles
    int jg = lane >> 3;             // 0..3 -> output col group (j0 = jg*8)
    int eg = lane & 7;              // edges eg + 8*i (i = 0..3)
    int j0 = jg * 8;

    float* myH = shH[w];
    const int*   myIdx = side ? sR : sS;
    const float* myP   = side ? P2b : P1b;

    // accumulators: 4 edges x 8 cols as u64 pairs, init from b2
    u64 acc[4][4];
    {
        const u64* bp = (const u64*)&sb2v[j0];
        u64 c0 = bp[0], c1 = bp[1], c2 = bp[2], c3 = bp[3];
        #pragma unroll
        for (int i = 0; i < 4; i++) {
            acc[i][0] = c0; acc[i][1] = c1; acc[i][2] = c2; acc[i][3] = c3;
        }
    }

    #pragma unroll 1
    for (int ch = 0; ch < 2; ch++) {
        // ------- gather phase: warp's 32 edges, k in [ch*32, ch*32+32) ----
        // MLP=4: batch 4 LDG.128 before consuming.
        #pragma unroll 1
        for (int it = 0; it < 16; it += 4) {
            float4 v[4];
            int    el[4];
            #pragma unroll
            for (int u = 0; u < 4; u++) {
                el[u] = (it + u) * 2 + half;        // 0..31
                int node = myIdx[w * 32 + el[u]];
                v[u] = *((const float4*)(myP + (size_t)node * 64) + ch * 8 + c);
            }
            #pragma unroll
            for (int u = 0; u < 4; u++) {
                float4 o;
                o.x = fmaxf(v[u].x + __shfl_xor_sync(0xffffffffu, v[u].x, 8), 0.f);
                o.y = fmaxf(v[u].y + __shfl_xor_sync(0xffffffffu, v[u].y, 8), 0.f);
                o.z = fmaxf(v[u].z + __shfl_xor_sync(0xffffffffu, v[u].z, 8), 0.f);
                o.w = fmaxf(v[u].w + __shfl_xor_sync(0xffffffffu, v[u].w, 8), 0.f);
                if (side == 0) {
                    // edge-major, stride 36: 16B-aligned vector store
                    *(float4*)&myH[el[u] * 36 + 4 * c] = o;
                }
            }
        }
        __syncwarp();

        // ------- mma phase over k in [ch*32, ch*32+32), kk blocks of 4 ----
        #pragma unroll 2
        for (int kkb = 0; kkb < 32; kkb += 4) {
            float4 h4[4];
            #pragma unroll
            for (int i = 0; i < 4; i++)
                h4[i] = *(const float4*)&myH[(eg + 8 * i) * 36 + kkb];

            #pragma unroll
            for (int q = 0; q < 4; q++) {
                int k = ch * 32 + kkb + q;
                const ulonglong2* wp = (const ulonglong2*)&sW[k * 32 + j0];
                ulonglong2 wa = wp[0];
                ulonglong2 wb = wp[1];
                float hq[4] = { q == 0 ? h4[0].x : q == 1 ? h4[0].y : q == 2 ? h4[0].z : h4[0].w,
                                q == 0 ? h4[1].x : q == 1 ? h4[1].y : q == 2 ? h4[1].z : h4[1].w,
                                q == 0 ? h4[2].x : q == 1 ? h4[2].y : q == 2 ? h4[2].z : h4[2].w,
                                q == 0 ? h4[3].x : q == 1 ? h4[3].y : q == 2 ? h4[3].z : h4[3].w };
                #pragma unroll
                for (int i = 0; i < 4; i++) {
                    u64 hp = pk2(hq[i], hq[i]);
                    fma2(acc[i][0], hp, wa.x);
                    fma2(acc[i][1], hp, wa.y);
                    fma2(acc[i][2], hp, wb.x);
                    fma2(acc[i][3], hp, wb.y);
                }
            }
        }
        __syncwarp();
    }

    // ------- epilogue: relu + vector atomic scatter -----------------------
    float* relb = g_rel + (size_t)b * NN * 32;
    #pragma unroll
    for (int i = 0; i < 4; i++) {
        int r = sR[w * 32 + eg + 8 * i];
        float f[8];
        up2(acc[i][0], f[0], f[1]); up2(acc[i][1], f[2], f[3]);
        up2(acc[i][2], f[4], f[5]); up2(acc[i][3], f[6], f[7]);
        #pragma unroll
        for (int q = 0; q < 8; q++) f[q] = fmaxf(f[q], 0.f);
        float* ptr = relb + (size_t)r * 32 + j0;
        asm volatile("red.global.add.v4.f32 [%0], {%1, %2, %3, %4};"
                     :: "l"(ptr), "f"(f[0]), "f"(f[1]), "f"(f[2]), "f"(f[3]) : "memory");
        asm volatile("red.global.add.v4.f32 [%0], {%1, %2, %3, %4};"
                     :: "l"(ptr + 4), "f"(f[4]), "f"(f[5]), "f"(f[6]), "f"(f[7]) : "memory");
    }
}

// ---------------------------------------------------------------------------
// Kernel C (R3-proven config): node MLP + residual. One thread per (b, n).
// 256-thread blocks, grid 128.
// ---------------------------------------------------------------------------
__global__ __launch_bounds__(256) void node_out_kernel(
    const float* __restrict__ particles,
    const float* __restrict__ W3,   // [48, 64]
    const float* __restrict__ b3,   // [64]
    const float* __restrict__ W4,   // [64, 16]
    const float* __restrict__ b4,   // [16]
    float* __restrict__ out)
{
    __shared__ float sW3[48 * 64];
    __shared__ float sW4[64 * 16];
    __shared__ float sb3[64];
    __shared__ float sb4[16];
    for (int i = threadIdx.x; i < 48 * 64; i += 256) sW3[i] = W3[i];
    for (int i = threadIdx.x; i < 64 * 16; i += 256) sW4[i] = W4[i];
    if (threadIdx.x < 64) sb3[threadIdx.x] = b3[threadIdx.x];
    if (threadIdx.x < 16) sb4[threadIdx.x] = b4[threadIdx.x];
    __syncthreads();

    int idx = blockIdx.x * 256 + threadIdx.x;

    float x[48];
    const float4* pp = (const float4*)(particles + (size_t)idx * 16);
    #pragma unroll
    for (int c = 0; c < 4; c++) {
        float4 v = pp[c];
        x[4 * c + 0] = v.x; x[4 * c + 1] = v.y; x[4 * c + 2] = v.z; x[4 * c + 3] = v.w;
    }
    const float4* rp = (const float4*)(g_rel + (size_t)idx * 32);
    #pragma unroll
    for (int c = 0; c < 8; c++) {
        float4 v = rp[c];
        x[16 + 4 * c + 0] = v.x; x[16 + 4 * c + 1] = v.y;
        x[16 + 4 * c + 2] = v.z; x[16 + 4 * c + 3] = v.w;
    }

    float delta[16];
    #pragma unroll
    for (int j = 0; j < 16; j++) delta[j] = sb4[j];

    #pragma unroll
    for (int half = 0; half < 2; half++) {
        float t[32];
        #pragma unroll
        for (int j = 0; j < 32; j++) t[j] = sb3[half * 32 + j];

        #pragma unroll
        for (int i = 0; i < 48; i++) {
            const float4* w = (const float4*)(sW3 + i * 64 + half * 32);
            float xv = x[i];
            #pragma unroll
            for (int j = 0; j < 8; j++) {
                float4 wv = w[j];
                t[4 * j + 0] += xv * wv.x;
                t[4 * j + 1] += xv * wv.y;
                t[4 * j + 2] += xv * wv.z;
                t[4 * j + 3] += xv * wv.w;
            }
        }
        #pragma unroll
        for (int j = 0; j < 32; j++) t[j] = fmaxf(t[j], 0.f);

        #pragma unroll
        for (int i = 0; i < 32; i++) {
            const float4* w = (const float4*)(sW4 + (half * 32 + i) * 16);
            float tv = t[i];
            #pragma unroll
            for (int j = 0; j < 4; j++) {
                float4 wv = w[j];
                delta[4 * j + 0] += tv * wv.x;
                delta[4 * j + 1] += tv * wv.y;
                delta[4 * j + 2] += tv * wv.z;
                delta[4 * j + 3] += tv * wv.w;
            }
        }
    }

    float4* outp = (float4*)(out + (size_t)idx * 16);
    #pragma unroll
    for (int c = 0; c < 4; c++) {
        outp[c] = make_float4(x[4 * c + 0] + delta[4 * c + 0],
                              x[4 * c + 1] + delta[4 * c + 1],
                              x[4 * c + 2] + delta[4 * c + 2],
                              x[4 * c + 3] + delta[4 * c + 3]);
    }
}

extern "C" void kernel_launch(void* const* d_in, const int* in_sizes, int n_in,
                              void* d_out, int out_size)
{
    const float* particles = (const float*)d_in[0];
    const int*   senders   = (const int*)d_in[1];
    const int*   receivers = (const int*)d_in[2];
    const float* W1 = (const float*)d_in[3];
    const float* b1 = (const float*)d_in[4];
    const float* W2 = (const float*)d_in[5];
    const float* b2 = (const float*)d_in[6];
    const float* W3 = (const float*)d_in[7];
    const float* b3 = (const float*)d_in[8];
    const float* W4 = (const float*)d_in[9];
    const float* b4 = (const float*)d_in[10];
    float* out = (float*)d_out;

    node_proj_kernel<<<(BB * NN) / 256, 256>>>(particles, W1, b1);

    dim3 egrid(EE / 256, BB);
    edge_kernel<<<egrid, 256>>>(senders, receivers, W2, b2);

    node_out_kernel<<<(BB * NN) / 256, 256>>>(particles, W3, b3, W4, b4, out);
}